// round 1
// baseline (speedup 1.0000x reference)
#include <cuda_runtime.h>
#include <math.h>

#define Bb 4
#define Tt 128
#define Ss 512
#define Hh 512

// Scratch (device globals; allocation-free per harness rules)
__device__ float g_pq[Bb * Tt * Hh];     // query @ W_s
__device__ float g_pe[Bb * Ss * Hh];     // encoder @ W_h
__device__ float g_score[Bb * Tt * Ss];  // scores -> alignment (in place)
__device__ float g_ctx[Bb * Tt * Hh];    // alignment @ encoder

__device__ __forceinline__ float tanh_fast(float x) {
    float y;
    asm("tanh.approx.f32 %0, %1;" : "=f"(y) : "f"(x));
    return y;
}

// ---------------------------------------------------------------------------
// Generic SGEMM: C[M,N] = concat_K(A0,A1) @ W, row-major, optional tanh
// epilogue, batched via blockIdx.z. 64x64 block tile, K-tile 16, 256 threads,
// 4x4 micro-tile per thread. A is staged transposed in smem.
// Requires: M%64==0, N%64==0, K%16==0, Ksplit%16==0, 16B-aligned pointers.
// ---------------------------------------------------------------------------
__global__ __launch_bounds__(256) void sgemm_kernel(
    const float* __restrict__ A0, const float* __restrict__ A1,
    const float* __restrict__ W, float* __restrict__ C,
    int M, int N, int K, int Ksplit, int lda0, int lda1,
    long batchA0, long batchW, long batchC, int do_tanh)
{
    __shared__ float Ast[16][64];  // [k][m]
    __shared__ float Wsm[16][64];  // [k][n]

    const int b = blockIdx.z;
    const float* A0b = A0 + (long)b * batchA0;
    const float* Wb  = W  + (long)b * batchW;
    float*       Cb  = C  + (long)b * batchC;

    const int row0 = blockIdx.y * 64;
    const int col0 = blockIdx.x * 64;
    const int tid = threadIdx.x;
    const int tx = tid & 15;   // 16 col groups
    const int ty = tid >> 4;   // 16 row groups

    float acc[4][4] = {};

    for (int k0 = 0; k0 < K; k0 += 16) {
        // --- stage A tile transposed: one float4 per thread ---
        {
            int r  = tid >> 2;          // 0..63  (m within tile)
            int kk = (tid & 3) * 4;     // 0..12  (k within tile)
            const float* src;
            if (k0 < Ksplit)
                src = A0b + (long)(row0 + r) * lda0 + (k0 + kk);
            else
                src = A1 + (long)(row0 + r) * lda1 + (k0 - Ksplit + kk);
            float4 av = *(const float4*)src;
            Ast[kk + 0][r] = av.x;
            Ast[kk + 1][r] = av.y;
            Ast[kk + 2][r] = av.z;
            Ast[kk + 3][r] = av.w;
        }
        // --- stage W tile: one float4 per thread ---
        {
            int r = tid >> 4;           // 0..15 (k within tile)
            int c = (tid & 15) * 4;     // 0..60 (n within tile)
            float4 wv = *(const float4*)(Wb + (long)(k0 + r) * N + col0 + c);
            *(float4*)&Wsm[r][c] = wv;
        }
        __syncthreads();

        #pragma unroll
        for (int kk = 0; kk < 16; kk++) {
            float4 a = *(const float4*)&Ast[kk][ty * 4];
            float4 w = *(const float4*)&Wsm[kk][tx * 4];
            float ar[4] = {a.x, a.y, a.z, a.w};
            float wr[4] = {w.x, w.y, w.z, w.w};
            #pragma unroll
            for (int i = 0; i < 4; i++)
                #pragma unroll
                for (int j = 0; j < 4; j++)
                    acc[i][j] += ar[i] * wr[j];
        }
        __syncthreads();
    }

    #pragma unroll
    for (int i = 0; i < 4; i++) {
        int r = row0 + ty * 4 + i;
        float4 o;
        o.x = acc[i][0]; o.y = acc[i][1]; o.z = acc[i][2]; o.w = acc[i][3];
        if (do_tanh) {
            o.x = tanhf(o.x); o.y = tanhf(o.y);
            o.z = tanhf(o.z); o.w = tanhf(o.w);
        }
        *(float4*)(Cb + (long)r * N + col0 + tx * 4) = o;
    }
}

// ---------------------------------------------------------------------------
// Score kernel: score[b,t,s] = sum_h v[h] * tanh(pq[b,t,h] + pe[b,s,h])
// Block tile: 16 t x 64 s, h chunked by 128 through smem. 256 threads,
// each owns a 2(t) x 2(s) register tile. MUFU.TANH bound by design.
// Smem pitch 132 makes the stride-1-row LDS.128 pattern conflict-free
// (132*tx mod 32 = 4*tx -> each 8-lane phase covers all 32 banks).
// ---------------------------------------------------------------------------
__global__ __launch_bounds__(256) void score_kernel(const float* __restrict__ v)
{
    __shared__ float pe_s[64][132];
    __shared__ float pq_s[16][132];
    __shared__ float v_s[128];

    const int b  = blockIdx.z;
    const int t0 = blockIdx.y * 16;
    const int s0 = blockIdx.x * 64;
    const int tid = threadIdx.x;
    const int tx = tid & 31;   // s lane
    const int ty = tid >> 5;   // t pair (0..7)

    float acc00 = 0.f, acc01 = 0.f, acc10 = 0.f, acc11 = 0.f;

    for (int h0 = 0; h0 < Hh; h0 += 128) {
        // stage pe tile: 64 rows x 128 floats (one warp per row, coalesced)
        for (int i = tid; i < 64 * 32; i += 256) {
            int r = i >> 5, c = (i & 31) * 4;
            float4 x = *(const float4*)(g_pe + (long)(b * Ss + s0 + r) * Hh + h0 + c);
            *(float4*)&pe_s[r][c] = x;
        }
        // stage pq tile: 16 rows x 128 floats
        for (int i = tid; i < 16 * 32; i += 256) {
            int r = i >> 5, c = (i & 31) * 4;
            float4 x = *(const float4*)(g_pq + (long)(b * Tt + t0 + r) * Hh + h0 + c);
            *(float4*)&pq_s[r][c] = x;
        }
        if (tid < 32)
            *(float4*)&v_s[tid * 4] = *(const float4*)(v + h0 + tid * 4);
        __syncthreads();

        #pragma unroll 8
        for (int hh = 0; hh < 128; hh += 4) {
            float4 vv = *(const float4*)&v_s[hh];
            float4 a0 = *(const float4*)&pq_s[ty * 2 + 0][hh];
            float4 a1 = *(const float4*)&pq_s[ty * 2 + 1][hh];
            float4 e0 = *(const float4*)&pe_s[tx][hh];
            float4 e1 = *(const float4*)&pe_s[tx + 32][hh];

            acc00 += vv.x * tanh_fast(a0.x + e0.x) + vv.y * tanh_fast(a0.y + e0.y)
                   + vv.z * tanh_fast(a0.z + e0.z) + vv.w * tanh_fast(a0.w + e0.w);
            acc01 += vv.x * tanh_fast(a0.x + e1.x) + vv.y * tanh_fast(a0.y + e1.y)
                   + vv.z * tanh_fast(a0.z + e1.z) + vv.w * tanh_fast(a0.w + e1.w);
            acc10 += vv.x * tanh_fast(a1.x + e0.x) + vv.y * tanh_fast(a1.y + e0.y)
                   + vv.z * tanh_fast(a1.z + e0.z) + vv.w * tanh_fast(a1.w + e0.w);
            acc11 += vv.x * tanh_fast(a1.x + e1.x) + vv.y * tanh_fast(a1.y + e1.y)
                   + vv.z * tanh_fast(a1.z + e1.z) + vv.w * tanh_fast(a1.w + e1.w);
        }
        __syncthreads();
    }

    const int t_a = t0 + ty * 2, t_b = t_a + 1;
    g_score[(long)(b * Tt + t_a) * Ss + s0 + tx]      = acc00;
    g_score[(long)(b * Tt + t_a) * Ss + s0 + tx + 32] = acc01;
    g_score[(long)(b * Tt + t_b) * Ss + s0 + tx]      = acc10;
    g_score[(long)(b * Tt + t_b) * Ss + s0 + tx + 32] = acc11;
}

// ---------------------------------------------------------------------------
// Masked softmax over S, in place on g_score. One block (128 threads) per
// (b,t) row of 512 floats; each thread owns one float4.
// ---------------------------------------------------------------------------
__global__ __launch_bounds__(128) void softmax_kernel(const int* __restrict__ src_len)
{
    const int row = blockIdx.x;          // b*T + t
    const int b = row / Tt;
    const int len = src_len[b];
    const int tid = threadIdx.x;
    float* sp = g_score + (long)row * Ss;

    __shared__ float redm[4];
    __shared__ float reds[4];

    const int sbase = tid * 4;
    float4 x4 = *(const float4*)(sp + sbase);
    float xv[4] = {x4.x, x4.y, x4.z, x4.w};
    #pragma unroll
    for (int i = 0; i < 4; i++)
        if (sbase + i >= len) xv[i] = -3.0e38f;

    float m = fmaxf(fmaxf(xv[0], xv[1]), fmaxf(xv[2], xv[3]));
    #pragma unroll
    for (int off = 16; off; off >>= 1)
        m = fmaxf(m, __shfl_xor_sync(0xffffffffu, m, off));
    if ((tid & 31) == 0) redm[tid >> 5] = m;
    __syncthreads();
    m = fmaxf(fmaxf(redm[0], redm[1]), fmaxf(redm[2], redm[3]));

    float e[4];
    float ssum = 0.f;
    #pragma unroll
    for (int i = 0; i < 4; i++) {
        e[i] = (sbase + i < len) ? expf(xv[i] - m) : 0.f;
        ssum += e[i];
    }
    #pragma unroll
    for (int off = 16; off; off >>= 1)
        ssum += __shfl_xor_sync(0xffffffffu, ssum, off);
    if ((tid & 31) == 0) reds[tid >> 5] = ssum;
    __syncthreads();
    ssum = reds[0] + reds[1] + reds[2] + reds[3];

    const float inv = 1.0f / ssum;
    float4 o;
    o.x = e[0] * inv; o.y = e[1] * inv; o.z = e[2] * inv; o.w = e[3] * inv;
    *(float4*)(sp + sbase) = o;
}

// ---------------------------------------------------------------------------
// Launch
// ---------------------------------------------------------------------------
extern "C" void kernel_launch(void* const* d_in, const int* in_sizes, int n_in,
                              void* d_out, int out_size)
{
    const float* query = (const float*)d_in[0];  // (B,T,H)
    const float* enc   = (const float*)d_in[1];  // (B,S,H)
    const int*   slen  = (const int*)d_in[2];    // (B,)
    const float* W_h   = (const float*)d_in[3];  // (H,H)
    const float* W_s   = (const float*)d_in[4];  // (H,H)
    const float* v     = (const float*)d_in[5];  // (H,)
    const float* W_out = (const float*)d_in[6];  // (2H,H)
    float* out = (float*)d_out;                  // (B,T,H)

    float *pq, *pe, *score, *ctx;
    cudaGetSymbolAddress((void**)&pq,    g_pq);
    cudaGetSymbolAddress((void**)&pe,    g_pe);
    cudaGetSymbolAddress((void**)&score, g_score);
    cudaGetSymbolAddress((void**)&ctx,   g_ctx);

    // 1) pe = encoder @ W_h   (M = B*S = 2048, N = 512, K = 512)
    sgemm_kernel<<<dim3(8, 32, 1), 256>>>(enc, enc, W_h, pe,
        2048, Hh, Hh, Hh, Hh, Hh, 0L, 0L, 0L, 0);

    // 2) pq = query @ W_s     (M = B*T = 512)
    sgemm_kernel<<<dim3(8, 8, 1), 256>>>(query, query, W_s, pq,
        512, Hh, Hh, Hh, Hh, Hh, 0L, 0L, 0L, 0);

    // 3) scores
    score_kernel<<<dim3(Ss / 64, Tt / 16, Bb), 256>>>(v);

    // 4) masked softmax (in place -> alignment)
    softmax_kernel<<<Bb * Tt, 128>>>(slen);

    // 5) context[b] = alignment[b] @ encoder[b]   (batched, M=T=128)
    sgemm_kernel<<<dim3(8, 2, Bb), 256>>>(score, score, enc, ctx,
        Tt, Hh, Ss, Ss, Ss, Ss,
        (long)Tt * Ss, (long)Ss * Hh, (long)Tt * Hh, 0);

    // 6) out = tanh(concat(context, query) @ W_out)  (M = B*T = 512, K = 1024)
    sgemm_kernel<<<dim3(8, 8, 1), 256>>>(ctx, query, W_out, out,
        512, Hh, 2 * Hh, Hh, Hh, Hh, 0L, 0L, 0L, 1);
}

// round 2
// speedup vs baseline: 1.3873x; 1.3873x over previous
#include <cuda_runtime.h>
#include <math.h>

#define Bb 4
#define Tt 128
#define Ss 512
#define Hh 512

// Scratch (device globals; allocation-free per harness rules)
__device__ float g_pq[Bb * Tt * Hh];     // query @ W_s
__device__ float g_pe[Bb * Ss * Hh];     // encoder @ W_h
__device__ float g_score[Bb * Tt * Ss];  // scores -> alignment (in place)
__device__ float g_ctx[Bb * Tt * Hh];    // alignment @ encoder

__device__ __forceinline__ float tanh_fast(float x) {
    float y;
    asm("tanh.approx.f32 %0, %1;" : "=f"(y) : "f"(x));
    return y;
}

// ---------------------------------------------------------------------------
// SGEMM v2: C[M,N] = concat_K(A0,A1) @ W, row-major, optional tanh epilogue,
// batched via blockIdx.z. Tile BM x BN x 32, (BM/4)*(BN/4) threads, 4x4
// micro-tile. Double-buffered smem + register prefetch: the LDG for chunk
// k+1 is issued before the 512-FFMA compute on chunk k, hiding L2 latency.
// A staged row-major with +1 pad (broadcast scalar reads, conflict-free).
// Requires: M%BM==0, N%BN==0, K%32==0, Ksplit%32==0, 16B-aligned pointers.
// ---------------------------------------------------------------------------
template <int BM, int BN, bool DO_TANH>
__global__ __launch_bounds__((BM / 4) * (BN / 4)) void sgemm2(
    const float* __restrict__ A0, const float* __restrict__ A1,
    const float* __restrict__ W, float* __restrict__ C,
    int N, int K, int Ksplit, int lda0, int lda1,
    long batchA0, long batchW, long batchC)
{
    constexpr int BK = 32;
    constexpr int THREADS = (BM / 4) * (BN / 4);
    constexpr int A_IT = (BM * BK) / (4 * THREADS);
    constexpr int W_IT = (BK * BN) / (4 * THREADS);

    __shared__ float As[2][BM][BK + 1];
    __shared__ float Ws[2][BK][BN];

    const int b = blockIdx.z;
    const float* A0b = A0 + (long)b * batchA0;
    const float* Wb  = W  + (long)b * batchW;
    float*       Cb  = C  + (long)b * batchC;

    const int row0 = blockIdx.y * BM;
    const int col0 = blockIdx.x * BN;
    const int tid = threadIdx.x;
    const int txn = tid % (BN / 4);
    const int tym = tid / (BN / 4);

    float4 aF[A_IT];
    float4 wF[W_IT];
    float acc[4][4] = {};

    auto loadChunk = [&](int k0) {
        #pragma unroll
        for (int i = 0; i < A_IT; i++) {
            int idx = tid + i * THREADS;
            int r  = idx / (BK / 4);
            int kc = (idx % (BK / 4)) * 4;
            int gk = k0 + kc;
            const float* src = (gk < Ksplit)
                ? A0b + (long)(row0 + r) * lda0 + gk
                : A1  + (long)(row0 + r) * lda1 + (gk - Ksplit);
            aF[i] = *(const float4*)src;
        }
        #pragma unroll
        for (int i = 0; i < W_IT; i++) {
            int idx = tid + i * THREADS;
            int r = idx / (BN / 4);
            int c = (idx % (BN / 4)) * 4;
            wF[i] = *(const float4*)(Wb + (long)(k0 + r) * N + col0 + c);
        }
    };
    auto storeChunk = [&](int buf) {
        #pragma unroll
        for (int i = 0; i < A_IT; i++) {
            int idx = tid + i * THREADS;
            int r  = idx / (BK / 4);
            int kc = (idx % (BK / 4)) * 4;
            As[buf][r][kc + 0] = aF[i].x;
            As[buf][r][kc + 1] = aF[i].y;
            As[buf][r][kc + 2] = aF[i].z;
            As[buf][r][kc + 3] = aF[i].w;
        }
        #pragma unroll
        for (int i = 0; i < W_IT; i++) {
            int idx = tid + i * THREADS;
            int r = idx / (BN / 4);
            int c = (idx % (BN / 4)) * 4;
            *(float4*)&Ws[buf][r][c] = wF[i];
        }
    };
    auto compute = [&](int buf) {
        #pragma unroll
        for (int kk = 0; kk < BK; kk++) {
            float a[4];
            #pragma unroll
            for (int i = 0; i < 4; i++) a[i] = As[buf][tym * 4 + i][kk];
            float4 w = *(const float4*)&Ws[buf][kk][txn * 4];
            float wr[4] = {w.x, w.y, w.z, w.w};
            #pragma unroll
            for (int i = 0; i < 4; i++)
                #pragma unroll
                for (int j = 0; j < 4; j++)
                    acc[i][j] += a[i] * wr[j];
        }
    };

    loadChunk(0);
    storeChunk(0);
    __syncthreads();

    int buf = 0;
    for (int k0 = BK; k0 < K; k0 += BK) {
        loadChunk(k0);          // LDG for next chunk, in flight during compute
        compute(buf);
        storeChunk(buf ^ 1);
        __syncthreads();
        buf ^= 1;
    }
    compute(buf);

    #pragma unroll
    for (int i = 0; i < 4; i++) {
        int r = row0 + tym * 4 + i;
        float4 o;
        o.x = acc[i][0]; o.y = acc[i][1]; o.z = acc[i][2]; o.w = acc[i][3];
        if (DO_TANH) {
            o.x = tanhf(o.x); o.y = tanhf(o.y);
            o.z = tanhf(o.z); o.w = tanhf(o.w);
        }
        *(float4*)(Cb + (long)r * N + col0 + txn * 4) = o;
    }
}

// ---------------------------------------------------------------------------
// Score kernel: score[b,t,s] = sum_h v[h] * tanh(pq[b,t,h] + pe[b,s,h])
// Block tile: 16 t x 64 s, h chunked by 128 through smem. 256 threads,
// each owns a 2(t) x 2(s) register tile. MUFU.TANH bound by design.
// ---------------------------------------------------------------------------
__global__ __launch_bounds__(256) void score_kernel(const float* __restrict__ v)
{
    __shared__ float pe_s[64][132];
    __shared__ float pq_s[16][132];
    __shared__ float v_s[128];

    const int b  = blockIdx.z;
    const int t0 = blockIdx.y * 16;
    const int s0 = blockIdx.x * 64;
    const int tid = threadIdx.x;
    const int tx = tid & 31;   // s lane
    const int ty = tid >> 5;   // t pair (0..7)

    float acc00 = 0.f, acc01 = 0.f, acc10 = 0.f, acc11 = 0.f;

    for (int h0 = 0; h0 < Hh; h0 += 128) {
        for (int i = tid; i < 64 * 32; i += 256) {
            int r = i >> 5, c = (i & 31) * 4;
            float4 x = *(const float4*)(g_pe + (long)(b * Ss + s0 + r) * Hh + h0 + c);
            *(float4*)&pe_s[r][c] = x;
        }
        for (int i = tid; i < 16 * 32; i += 256) {
            int r = i >> 5, c = (i & 31) * 4;
            float4 x = *(const float4*)(g_pq + (long)(b * Tt + t0 + r) * Hh + h0 + c);
            *(float4*)&pq_s[r][c] = x;
        }
        if (tid < 32)
            *(float4*)&v_s[tid * 4] = *(const float4*)(v + h0 + tid * 4);
        __syncthreads();

        #pragma unroll 8
        for (int hh = 0; hh < 128; hh += 4) {
            float4 vv = *(const float4*)&v_s[hh];
            float4 a0 = *(const float4*)&pq_s[ty * 2 + 0][hh];
            float4 a1 = *(const float4*)&pq_s[ty * 2 + 1][hh];
            float4 e0 = *(const float4*)&pe_s[tx][hh];
            float4 e1 = *(const float4*)&pe_s[tx + 32][hh];

            acc00 += vv.x * tanh_fast(a0.x + e0.x) + vv.y * tanh_fast(a0.y + e0.y)
                   + vv.z * tanh_fast(a0.z + e0.z) + vv.w * tanh_fast(a0.w + e0.w);
            acc01 += vv.x * tanh_fast(a0.x + e1.x) + vv.y * tanh_fast(a0.y + e1.y)
                   + vv.z * tanh_fast(a0.z + e1.z) + vv.w * tanh_fast(a0.w + e1.w);
            acc10 += vv.x * tanh_fast(a1.x + e0.x) + vv.y * tanh_fast(a1.y + e0.y)
                   + vv.z * tanh_fast(a1.z + e0.z) + vv.w * tanh_fast(a1.w + e0.w);
            acc11 += vv.x * tanh_fast(a1.x + e1.x) + vv.y * tanh_fast(a1.y + e1.y)
                   + vv.z * tanh_fast(a1.z + e1.z) + vv.w * tanh_fast(a1.w + e1.w);
        }
        __syncthreads();
    }

    const int t_a = t0 + ty * 2, t_b = t_a + 1;
    g_score[(long)(b * Tt + t_a) * Ss + s0 + tx]      = acc00;
    g_score[(long)(b * Tt + t_a) * Ss + s0 + tx + 32] = acc01;
    g_score[(long)(b * Tt + t_b) * Ss + s0 + tx]      = acc10;
    g_score[(long)(b * Tt + t_b) * Ss + s0 + tx + 32] = acc11;
}

// ---------------------------------------------------------------------------
// Masked softmax over S, in place on g_score. One block (128 threads) per
// (b,t) row of 512 floats; each thread owns one float4.
// ---------------------------------------------------------------------------
__global__ __launch_bounds__(128) void softmax_kernel(const int* __restrict__ src_len)
{
    const int row = blockIdx.x;          // b*T + t
    const int b = row / Tt;
    const int len = src_len[b];
    const int tid = threadIdx.x;
    float* sp = g_score + (long)row * Ss;

    __shared__ float redm[4];
    __shared__ float reds[4];

    const int sbase = tid * 4;
    float4 x4 = *(const float4*)(sp + sbase);
    float xv[4] = {x4.x, x4.y, x4.z, x4.w};
    #pragma unroll
    for (int i = 0; i < 4; i++)
        if (sbase + i >= len) xv[i] = -3.0e38f;

    float m = fmaxf(fmaxf(xv[0], xv[1]), fmaxf(xv[2], xv[3]));
    #pragma unroll
    for (int off = 16; off; off >>= 1)
        m = fmaxf(m, __shfl_xor_sync(0xffffffffu, m, off));
    if ((tid & 31) == 0) redm[tid >> 5] = m;
    __syncthreads();
    m = fmaxf(fmaxf(redm[0], redm[1]), fmaxf(redm[2], redm[3]));

    float e[4];
    float ssum = 0.f;
    #pragma unroll
    for (int i = 0; i < 4; i++) {
        e[i] = (sbase + i < len) ? expf(xv[i] - m) : 0.f;
        ssum += e[i];
    }
    #pragma unroll
    for (int off = 16; off; off >>= 1)
        ssum += __shfl_xor_sync(0xffffffffu, ssum, off);
    if ((tid & 31) == 0) reds[tid >> 5] = ssum;
    __syncthreads();
    ssum = reds[0] + reds[1] + reds[2] + reds[3];

    const float inv = 1.0f / ssum;
    float4 o;
    o.x = e[0] * inv; o.y = e[1] * inv; o.z = e[2] * inv; o.w = e[3] * inv;
    *(float4*)(sp + sbase) = o;
}

// ---------------------------------------------------------------------------
// Launch
// ---------------------------------------------------------------------------
extern "C" void kernel_launch(void* const* d_in, const int* in_sizes, int n_in,
                              void* d_out, int out_size)
{
    const float* query = (const float*)d_in[0];  // (B,T,H)
    const float* enc   = (const float*)d_in[1];  // (B,S,H)
    const int*   slen  = (const int*)d_in[2];    // (B,)
    const float* W_h   = (const float*)d_in[3];  // (H,H)
    const float* W_s   = (const float*)d_in[4];  // (H,H)
    const float* v     = (const float*)d_in[5];  // (H,)
    const float* W_out = (const float*)d_in[6];  // (2H,H)
    float* out = (float*)d_out;                  // (B,T,H)

    float *pq, *pe, *score, *ctx;
    cudaGetSymbolAddress((void**)&pq,    g_pq);
    cudaGetSymbolAddress((void**)&pe,    g_pe);
    cudaGetSymbolAddress((void**)&score, g_score);
    cudaGetSymbolAddress((void**)&ctx,   g_ctx);

    // 1) pe = encoder @ W_h   (M = B*S = 2048, N = 512, K = 512) : 512 blocks
    sgemm2<32, 64, false><<<dim3(8, 64, 1), 128>>>(enc, enc, W_h, pe,
        Hh, Hh, Hh, Hh, Hh, 0L, 0L, 0L);

    // 2) pq = query @ W_s     (M = B*T = 512) : 128 blocks
    sgemm2<32, 64, false><<<dim3(8, 16, 1), 128>>>(query, query, W_s, pq,
        Hh, Hh, Hh, Hh, Hh, 0L, 0L, 0L);

    // 3) scores
    score_kernel<<<dim3(Ss / 64, Tt / 16, Bb), 256>>>(v);

    // 4) masked softmax (in place -> alignment)
    softmax_kernel<<<Bb * Tt, 128>>>(slen);

    // 5) context[b] = alignment[b] @ encoder[b]  (M=T=128, K=S) : 128 blocks
    sgemm2<32, 64, false><<<dim3(8, 4, Bb), 128>>>(score, score, enc, ctx,
        Hh, Ss, Ss, Ss, Ss, (long)Tt * Ss, (long)Ss * Hh, (long)Tt * Hh);

    // 6) out = tanh(concat(context, query) @ W_out)  (M=512, K=1024) : 128 blocks
    sgemm2<32, 64, true><<<dim3(8, 16, 1), 128>>>(ctx, query, W_out, out,
        Hh, 2 * Hh, Hh, Hh, Hh, 0L, 0L, 0L);
}